// round 13
// baseline (speedup 1.0000x reference)
#include <cuda_runtime.h>
#include <cuda_fp16.h>
#include <cstdint>
#include <math.h>

#define HIDDEN 2048
#define NHEADS 16
#define HDIM 128
#define FFDIM 5632
#define BATCHN 2
#define SEQ 2048
#define NTOK (BATCHN*SEQ)   // 4096

// ---------------- scratch ----------------
__device__ __half g_xnh[NTOK*HIDDEN];
__device__ __half g_qh[NTOK*HIDDEN];
__device__ __half g_kh[NTOK*HIDDEN];
__device__ __half g_vth[BATCHN*NHEADS*HDIM*SEQ];   // V transposed: [b,h,dim,seq]
__device__ __half g_aoh[NTOK*HIDDEN];
__device__ float  g_h[NTOK*HIDDEN];
__device__ __half g_ffnh[NTOK*HIDDEN];
__device__ __half g_g1h[(size_t)NTOK*FFDIM];
__device__ float  g_invf[64];
// fp16 TRANSPOSED weights [N, K] K-major
__device__ __half g_wqkv[3*HIDDEN*HIDDEN];         // wq | wk | wv concatenated
__device__ __half g_wo[HIDDEN*HIDDEN];
__device__ __half g_w1[(size_t)HIDDEN*FFDIM];
__device__ __half g_w3[(size_t)HIDDEN*FFDIM];
__device__ __half g_w2[(size_t)FFDIM*HIDDEN];

// ---------------- helpers ----------------
__device__ __forceinline__ unsigned smem_u32(const void* p){
    return (unsigned)__cvta_generic_to_shared(p);
}
__device__ __forceinline__ void cp16(unsigned s, const void* g){
    asm volatile("cp.async.cg.shared.global [%0], [%1], 16;\n" :: "r"(s), "l"(g));
}
#define CP_COMMIT() asm volatile("cp.async.commit_group;\n")
#define CP_WAIT(n)  asm volatile("cp.async.wait_group %0;\n" :: "n"(n))

__device__ __forceinline__ void mma_h(float c[4],
        unsigned a0, unsigned a1, unsigned a2, unsigned a3,
        unsigned b0, unsigned b1){
    asm volatile("mma.sync.aligned.m16n8k16.row.col.f32.f16.f16.f32 "
        "{%0,%1,%2,%3},{%4,%5,%6,%7},{%8,%9},{%0,%1,%2,%3};\n"
        : "+f"(c[0]), "+f"(c[1]), "+f"(c[2]), "+f"(c[3])
        : "r"(a0), "r"(a1), "r"(a2), "r"(a3), "r"(b0), "r"(b1));
}
__device__ __forceinline__ void ldm_x4(unsigned &r0, unsigned &r1, unsigned &r2, unsigned &r3,
                                       unsigned addr){
    asm volatile("ldmatrix.sync.aligned.m8n8.x4.shared.b16 {%0,%1,%2,%3}, [%4];"
        : "=r"(r0), "=r"(r1), "=r"(r2), "=r"(r3) : "r"(addr));
}

__device__ __forceinline__ float warpReduceSum(float v){
    #pragma unroll
    for (int o=16;o;o>>=1) v += __shfl_xor_sync(0xffffffffu, v, o);
    return v;
}
__device__ float blockReduceSum(float v){   // 256 threads
    __shared__ float s[8]; __shared__ float tot;
    int lane = threadIdx.x & 31, w = threadIdx.x >> 5;
    v = warpReduceSum(v);
    if (!lane) s[w] = v;
    __syncthreads();
    if (w == 0){
        float t = (lane < 8) ? s[lane] : 0.f;
        t = warpReduceSum(t);
        if (!lane) tot = t;
    }
    __syncthreads();
    return tot;
}

// ======== fp16 GEMM v3: BM=128, BN=256, BK=64; 512 thr (16 warps of 32x64);
// 3-stage pipeline + ldmatrix; 1 CTA/SM (smem 162KB). ========
#define HSTR 72
#define ATILE (128*HSTR)                 // A stage: 128 rows
#define BTILE (256*HSTR)                 // B stage: 256 rows
#define STG   (ATILE+BTILE)
#define SMEM_H (3*STG*2)                 // 165888 B

__global__ void __launch_bounds__(512, 1)
gemm_h(const __half* __restrict__ A, int lda,
       const __half* __restrict__ Bt, int ldb,
       float* __restrict__ C, int ldc,
       const float* __restrict__ Res,
       int K, int npm, int npn)
{
    extern __shared__ __half sh[];

    int pid = blockIdx.x;
    const int GROUP = 16;
    int npg = GROUP * npn;
    int gid = pid / npg;
    int firstm = gid * GROUP;
    int gsz = min(GROUP, npm - firstm);
    int pm = firstm + (pid % npg) % gsz;
    int pn = (pid % npg) / gsz;
    int m0 = pm * 128, n0 = pn * 256;

    int KT = K / 64;
    int tid = threadIdx.x;
    int wid = tid >> 5, lane = tid & 31;
    int wm = (wid & 3) * 32;
    int wn = (wid >> 2) * 64;
    int rl = lane >> 2, l3 = lane & 3;

    int arow = (wm + (lane & 15)) * HSTR + (lane >> 4) * 8;
    int brow = (wn + (lane & 7) + ((lane >> 4) << 3)) * HSTR + (((lane >> 3) & 1) << 3);

    auto loadAB = [&](int st, int kt){
        __half* sa = sh + st * STG;
        __half* sb = sa + ATILE;
        int c = tid & 7;
        int r0 = tid >> 3;                 // 64 rows per pass
        const __half* ga = A  + (long long)m0 * lda + kt * 64 + c * 8;
        const __half* gb = Bt + (long long)n0 * ldb + kt * 64 + c * 8;
        #pragma unroll
        for (int w = 0; w < 2; w++){
            int row = r0 + 64 * w;
            cp16(smem_u32(sa + row * HSTR + c * 8), ga + (long long)row * lda);
        }
        #pragma unroll
        for (int w = 0; w < 4; w++){
            int row = r0 + 64 * w;
            cp16(smem_u32(sb + row * HSTR + c * 8), gb + (long long)row * ldb);
        }
    };

    float acc[2][8][4];
    #pragma unroll
    for (int i=0;i<2;i++)
        #pragma unroll
        for (int j=0;j<8;j++)
            #pragma unroll
            for (int r=0;r<4;r++) acc[i][j][r] = 0.f;

    loadAB(0, 0); CP_COMMIT();
    if (KT > 1) loadAB(1, 1);
    CP_COMMIT();

    for (int kt = 0; kt < KT; kt++){
        int cur = kt % 3;
        CP_WAIT(1);
        __syncthreads();
        if (kt + 2 < KT) loadAB((kt + 2) % 3, kt + 2);
        CP_COMMIT();

        const __half* sa = sh + cur * STG;
        const __half* sb = sa + ATILE;
        unsigned abase = smem_u32(sa) + arow * 2;
        unsigned bbase = smem_u32(sb) + brow * 2;
        #pragma unroll
        for (int ks = 0; ks < 4; ks++){
            unsigned koff = ks * 32;
            unsigned a[2][4];
            #pragma unroll
            for (int mi = 0; mi < 2; mi++)
                ldm_x4(a[mi][0], a[mi][1], a[mi][2], a[mi][3],
                       abase + mi * (16 * HSTR * 2) + koff);
            #pragma unroll
            for (int nip = 0; nip < 4; nip++){
                unsigned b0, b1, b2, b3;
                ldm_x4(b0, b1, b2, b3, bbase + nip * (16 * HSTR * 2) + koff);
                #pragma unroll
                for (int mi = 0; mi < 2; mi++){
                    mma_h(acc[mi][2*nip],   a[mi][0], a[mi][1], a[mi][2], a[mi][3], b0, b1);
                    mma_h(acc[mi][2*nip+1], a[mi][0], a[mi][1], a[mi][2], a[mi][3], b2, b3);
                }
            }
        }
    }

    #pragma unroll
    for (int mi = 0; mi < 2; mi++){
        #pragma unroll
        for (int ni = 0; ni < 8; ni++){
            int row = m0 + wm + mi * 16 + rl;
            int col = n0 + wn + ni * 8 + l3 * 2;
            float v0 = acc[mi][ni][0];
            float v1 = acc[mi][ni][1];
            float v2 = acc[mi][ni][2];
            float v3 = acc[mi][ni][3];
            if (Res){
                float2 r01 = *(const float2*)(Res + (long long)row * ldc + col);
                float2 r23 = *(const float2*)(Res + (long long)(row + 8) * ldc + col);
                v0 += r01.x; v1 += r01.y; v2 += r23.x; v3 += r23.y;
            }
            *(float2*)(C + (long long)row * ldc + col)       = make_float2(v0, v1);
            *(float2*)(C + (long long)(row + 8) * ldc + col) = make_float2(v2, v3);
        }
    }
}

// ======== merged QKV gemm v3 (BN=256): epilogue rope->fp16 / V-transpose ========
__global__ void __launch_bounds__(512, 1)
gemm_qkv(const __half* __restrict__ A, int lda,
         const __half* __restrict__ Bt, int ldb,
         __half* __restrict__ Qh, __half* __restrict__ Kh, __half* __restrict__ Vt,
         const int* __restrict__ pos, int K, int npm, int npn)
{
    extern __shared__ __half sh[];

    int pid = blockIdx.x;
    const int GROUP = 16;
    int npg = GROUP * npn;
    int gid = pid / npg;
    int firstm = gid * GROUP;
    int gsz = min(GROUP, npm - firstm);
    int pm = firstm + (pid % npg) % gsz;
    int pn = (pid % npg) / gsz;
    int m0 = pm * 128, n0 = pn * 256;

    int KT = K / 64;
    int tid = threadIdx.x;
    int wid = tid >> 5, lane = tid & 31;
    int wm = (wid & 3) * 32;
    int wn = (wid >> 2) * 64;
    int rl = lane >> 2, l3 = lane & 3;

    int arow = (wm + (lane & 15)) * HSTR + (lane >> 4) * 8;
    int brow = (wn + (lane & 7) + ((lane >> 4) << 3)) * HSTR + (((lane >> 3) & 1) << 3);

    auto loadAB = [&](int st, int kt){
        __half* sa = sh + st * STG;
        __half* sb = sa + ATILE;
        int c = tid & 7;
        int r0 = tid >> 3;
        const __half* ga = A  + (long long)m0 * lda + kt * 64 + c * 8;
        const __half* gb = Bt + (long long)n0 * ldb + kt * 64 + c * 8;
        #pragma unroll
        for (int w = 0; w < 2; w++){
            int row = r0 + 64 * w;
            cp16(smem_u32(sa + row * HSTR + c * 8), ga + (long long)row * lda);
        }
        #pragma unroll
        for (int w = 0; w < 4; w++){
            int row = r0 + 64 * w;
            cp16(smem_u32(sb + row * HSTR + c * 8), gb + (long long)row * ldb);
        }
    };

    float acc[2][8][4];
    #pragma unroll
    for (int i=0;i<2;i++)
        #pragma unroll
        for (int j=0;j<8;j++)
            #pragma unroll
            for (int r=0;r<4;r++) acc[i][j][r] = 0.f;

    loadAB(0, 0); CP_COMMIT();
    if (KT > 1) loadAB(1, 1);
    CP_COMMIT();

    for (int kt = 0; kt < KT; kt++){
        int cur = kt % 3;
        CP_WAIT(1);
        __syncthreads();
        if (kt + 2 < KT) loadAB((kt + 2) % 3, kt + 2);
        CP_COMMIT();

        const __half* sa = sh + cur * STG;
        const __half* sb = sa + ATILE;
        unsigned abase = smem_u32(sa) + arow * 2;
        unsigned bbase = smem_u32(sb) + brow * 2;
        #pragma unroll
        for (int ks = 0; ks < 4; ks++){
            unsigned koff = ks * 32;
            unsigned a[2][4];
            #pragma unroll
            for (int mi = 0; mi < 2; mi++)
                ldm_x4(a[mi][0], a[mi][1], a[mi][2], a[mi][3],
                       abase + mi * (16 * HSTR * 2) + koff);
            #pragma unroll
            for (int nip = 0; nip < 4; nip++){
                unsigned b0, b1, b2, b3;
                ldm_x4(b0, b1, b2, b3, bbase + nip * (16 * HSTR * 2) + koff);
                #pragma unroll
                for (int mi = 0; mi < 2; mi++){
                    mma_h(acc[mi][2*nip],   a[mi][0], a[mi][1], a[mi][2], a[mi][3], b0, b1);
                    mma_h(acc[mi][2*nip+1], a[mi][0], a[mi][1], a[mi][2], a[mi][3], b2, b3);
                }
            }
        }
    }

    #pragma unroll
    for (int mi = 0; mi < 2; mi++){
        #pragma unroll
        for (int ni = 0; ni < 8; ni++){
            int row = m0 + wm + mi * 16 + rl;
            int ncol = n0 + wn + ni * 8 + l3 * 2;   // global 0..6143
            int wsel = ncol >> 11;                  // 0=q,1=k,2=v
            int col  = ncol & 2047;
            float v0 = acc[mi][ni][0];
            float v1 = acc[mi][ni][1];
            float v2 = acc[mi][ni][2];
            float v3 = acc[mi][ni][3];
            if (wsel < 2){
                int i = (col & 127) >> 1;
                float invf = g_invf[i];
                float a0 = (float)pos[row] * invf;
                float a1 = (float)pos[row + 8] * invf;
                float s0, c0, s1, c1;
                sincosf(a0, &s0, &c0);
                sincosf(a1, &s1, &c1);
                float t0 = v0 * c0 - v1 * s0;
                float t1 = v1 * c0 + v0 * s0;
                float t2 = v2 * c1 - v3 * s1;
                float t3 = v3 * c1 + v2 * s1;
                __half* O = wsel ? Kh : Qh;
                *(__half2*)(O + (long long)row * 2048 + col)       = __floats2half2_rn(t0, t1);
                *(__half2*)(O + (long long)(row + 8) * 2048 + col) = __floats2half2_rn(t2, t3);
            } else {
                int b = row >> 11, seq = row & 2047;
                int h = col >> 7,  dim = col & 127;
                __half* base = Vt + ((long long)(b * 16 + h) * 128) * 2048;
                base[(long long)dim * 2048 + seq]           = __float2half_rn(v0);
                base[(long long)(dim + 1) * 2048 + seq]     = __float2half_rn(v1);
                base[(long long)dim * 2048 + seq + 8]       = __float2half_rn(v2);
                base[(long long)(dim + 1) * 2048 + seq + 8] = __float2half_rn(v3);
            }
        }
    }
}

// ======== fused FFN v3 (BN=128 outputs, 512 thr): g1h = fp16(silu(A@W1^T)*(A@W3^T)) =
#define FBT (128*HSTR)
#define FSTG (ATILE + 2*FBT)
#define SMEM_F (3*FSTG*2)                // 165888 B

__global__ void __launch_bounds__(512, 1)
gemm_ff(const __half* __restrict__ A, int lda,
        const __half* __restrict__ B1t, const __half* __restrict__ B3t, int ldb,
        __half* __restrict__ O, int ldo,
        int K, int npm, int npn)
{
    extern __shared__ __half sh[];

    int pid = blockIdx.x;
    const int GROUP = 16;
    int npg = GROUP * npn;
    int gid = pid / npg;
    int firstm = gid * GROUP;
    int gsz = min(GROUP, npm - firstm);
    int pm = firstm + (pid % npg) % gsz;
    int pn = (pid % npg) / gsz;
    int m0 = pm * 128, n0 = pn * 128;

    int KT = K / 64;
    int tid = threadIdx.x;
    int wid = tid >> 5, lane = tid & 31;
    int wm = (wid & 3) * 32;
    int wn = (wid >> 2) * 32;
    int rl = lane >> 2, l3 = lane & 3;

    int arow = (wm + (lane & 15)) * HSTR + (lane >> 4) * 8;
    int brow = (wn + (lane & 7) + ((lane >> 4) << 3)) * HSTR + (((lane >> 3) & 1) << 3);

    auto loadAB = [&](int st, int kt){
        __half* sa  = sh + st * FSTG;
        __half* sb1 = sa + ATILE;
        __half* sb3 = sb1 + FBT;
        int c = tid & 7;
        int r0 = tid >> 3;                 // 64 rows per pass
        const __half* ga = A + (long long)m0 * lda + kt * 64 + c * 8;
        #pragma unroll
        for (int w = 0; w < 2; w++){
            int row = r0 + 64 * w;
            cp16(smem_u32(sa + row * HSTR + c * 8), ga + (long long)row * lda);
        }
        const __half* g1 = B1t + (long long)n0 * ldb + kt * 64 + c * 8;
        const __half* g3 = B3t + (long long)n0 * ldb + kt * 64 + c * 8;
        #pragma unroll
        for (int w = 0; w < 2; w++){
            int row = r0 + 64 * w;
            cp16(smem_u32(sb1 + row * HSTR + c * 8), g1 + (long long)row * ldb);
        }
        #pragma unroll
        for (int w = 0; w < 2; w++){
            int row = r0 + 64 * w;
            cp16(smem_u32(sb3 + row * HSTR + c * 8), g3 + (long long)row * ldb);
        }
    };

    float ac1[2][4][4], ac3[2][4][4];
    #pragma unroll
    for (int i=0;i<2;i++)
        #pragma unroll
        for (int j=0;j<4;j++)
            #pragma unroll
            for (int r=0;r<4;r++){ ac1[i][j][r] = 0.f; ac3[i][j][r] = 0.f; }

    loadAB(0, 0); CP_COMMIT();
    if (KT > 1) loadAB(1, 1);
    CP_COMMIT();

    for (int kt = 0; kt < KT; kt++){
        int cur = kt % 3;
        CP_WAIT(1);
        __syncthreads();
        if (kt + 2 < KT) loadAB((kt + 2) % 3, kt + 2);
        CP_COMMIT();

        const __half* sa  = sh + cur * FSTG;
        const __half* sb1 = sa + ATILE;
        const __half* sb3 = sb1 + FBT;
        unsigned abase  = smem_u32(sa)  + arow * 2;
        unsigned b1base = smem_u32(sb1) + brow * 2;
        unsigned b3base = smem_u32(sb3) + brow * 2;
        #pragma unroll
        for (int ks = 0; ks < 4; ks++){
            unsigned koff = ks * 32;
            unsigned a[2][4];
            #pragma unroll
            for (int mi = 0; mi < 2; mi++)
                ldm_x4(a[mi][0], a[mi][1], a[mi][2], a[mi][3],
                       abase + mi * (16 * HSTR * 2) + koff);
            #pragma unroll
            for (int nip = 0; nip < 2; nip++){
                unsigned b0, b1, b2, b3;
                ldm_x4(b0, b1, b2, b3, b1base + nip * (16 * HSTR * 2) + koff);
                #pragma unroll
                for (int mi = 0; mi < 2; mi++){
                    mma_h(ac1[mi][2*nip],   a[mi][0], a[mi][1], a[mi][2], a[mi][3], b0, b1);
                    mma_h(ac1[mi][2*nip+1], a[mi][0], a[mi][1], a[mi][2], a[mi][3], b2, b3);
                }
                unsigned c0, c1, c2, c3;
                ldm_x4(c0, c1, c2, c3, b3base + nip * (16 * HSTR * 2) + koff);
                #pragma unroll
                for (int mi = 0; mi < 2; mi++){
                    mma_h(ac3[mi][2*nip],   a[mi][0], a[mi][1], a[mi][2], a[mi][3], c0, c1);
                    mma_h(ac3[mi][2*nip+1], a[mi][0], a[mi][1], a[mi][2], a[mi][3], c2, c3);
                }
            }
        }
    }

    #pragma unroll
    for (int mi = 0; mi < 2; mi++){
        #pragma unroll
        for (int ni = 0; ni < 4; ni++){
            int row = m0 + wm + mi * 16 + rl;
            int col = n0 + wn + ni * 8 + l3 * 2;
            float x0 = ac1[mi][ni][0], x1 = ac1[mi][ni][1];
            float x2 = ac1[mi][ni][2], x3 = ac1[mi][ni][3];
            float y0 = ac3[mi][ni][0], y1 = ac3[mi][ni][1];
            float y2 = ac3[mi][ni][2], y3 = ac3[mi][ni][3];
            float s0 = x0 / (1.0f + __expf(-x0)) * y0;
            float s1 = x1 / (1.0f + __expf(-x1)) * y1;
            float s2 = x2 / (1.0f + __expf(-x2)) * y2;
            float s3 = x3 / (1.0f + __expf(-x3)) * y3;
            *(__half2*)(O + (long long)row * ldo + col)       = __floats2half2_rn(s0, s1);
            *(__half2*)(O + (long long)(row + 8) * ldo + col) = __floats2half2_rn(s2, s3);
        }
    }
}

// ---------------- flash attention (unchanged R12 winner) ----------------
#define FKSTR 136
#define FLASH_SMEM ((2*128*FKSTR + 2*128*FKSTR + 8*16*FKSTR)*2)

__global__ void __launch_bounds__(256, 1)
flash_h(const __half* __restrict__ Q, const __half* __restrict__ K,
        const __half* __restrict__ Vt, __half* __restrict__ O,
        float alpha)
{
    extern __shared__ __half sh[];
    __half* sKb  = sh;
    __half* sVtb = sh + 2*128*FKSTR;
    __half* sP   = sVtb + 2*128*FKSTR;

    int z = blockIdx.y;
    int b = z >> 4, h = z & 15;
    int qt = (gridDim.x - 1) - blockIdx.x;
    int q0 = qt * 128;
    const __half* Qg  = Q + ((long long)b * SEQ) * HIDDEN + h * HDIM;
    const __half* Kg  = K + ((long long)b * SEQ) * HIDDEN + h * HDIM;
    const __half* Vtg = Vt + ((long long)z * HDIM) * SEQ;
    __half* Og = O + ((long long)b * SEQ) * HIDDEN + h * HDIM;

    int tid = threadIdx.x, wid = tid >> 5, lane = tid & 31;
    int rl = lane >> 2, l3 = lane & 3;
    int qr = q0 + wid * 16;
    __half* sPw = sP + wid * 16 * FKSTR;

    int brow = ((lane & 7) + ((lane >> 4) << 3)) * FKSTR + (((lane >> 3) & 1) << 3);
    int parow = (lane & 15) * FKSTR + ((lane >> 4) << 3);

    unsigned qf[8][4];
    #pragma unroll
    for (int ks = 0; ks < 8; ks++){
        const __half* p0 = Qg + (long long)(qr + rl) * HIDDEN + ks * 16 + l3 * 2;
        const __half* p1 = Qg + (long long)(qr + rl + 8) * HIDDEN + ks * 16 + l3 * 2;
        qf[ks][0] = *(const unsigned*)(p0);
        qf[ks][1] = *(const unsigned*)(p1);
        qf[ks][2] = *(const unsigned*)(p0 + 8);
        qf[ks][3] = *(const unsigned*)(p1 + 8);
    }

    float Oa[16][4];
    #pragma unroll
    for (int ni = 0; ni < 16; ni++){
        Oa[ni][0] = 0.f; Oa[ni][1] = 0.f; Oa[ni][2] = 0.f; Oa[ni][3] = 0.f;
    }
    float m0r = -1e30f, m1r = -1e30f, l0r = 0.f, l1r = 0.f;

    auto loadKV = [&](int buf, int t){
        int c = tid & 15, r0 = tid >> 4;
        const __half* kp = Kg + (long long)(t * 128) * HIDDEN + c * 8;
        __half* dk = sKb + buf * 128 * FKSTR;
        #pragma unroll
        for (int w = 0; w < 8; w++){
            int row = r0 + 16 * w;
            cp16(smem_u32(dk + row * FKSTR + c * 8), kp + (long long)row * HIDDEN);
        }
        const __half* vp = Vtg + t * 128 + c * 8;
        __half* dv = sVtb + buf * 128 * FKSTR;
        #pragma unroll
        for (int w = 0; w < 8; w++){
            int row = r0 + 16 * w;
            cp16(smem_u32(dv + row * FKSTR + c * 8), vp + (long long)row * SEQ);
        }
    };

    int nt = qt + 1;
    loadKV(0, 0); CP_COMMIT();

    for (int t = 0; t < nt; t++){
        int buf = t & 1;
        if (t + 1 < nt){
            loadKV(buf ^ 1, t + 1);
            CP_COMMIT();
            CP_WAIT(1);
        } else {
            CP_WAIT(0);
        }
        __syncthreads();
        const __half* cK  = sKb  + buf * 128 * FKSTR;
        const __half* cVt = sVtb + buf * 128 * FKSTR;
        unsigned kbase = smem_u32(cK)  + brow * 2;
        unsigned vbase = smem_u32(cVt) + brow * 2;
        int diag = (t == qt);
        int k0 = t * 128;

        float Sa[16][4];
        #pragma unroll
        for (int ni = 0; ni < 16; ni++){
            Sa[ni][0]=0.f; Sa[ni][1]=0.f; Sa[ni][2]=0.f; Sa[ni][3]=0.f;
        }
        #pragma unroll
        for (int ks = 0; ks < 8; ks++){
            unsigned koff = ks * 32;
            #pragma unroll
            for (int nip = 0; nip < 8; nip++){
                unsigned b0, b1, b2, b3;
                ldm_x4(b0, b1, b2, b3, kbase + nip * (16 * FKSTR * 2) + koff);
                mma_h(Sa[2*nip],   qf[ks][0], qf[ks][1], qf[ks][2], qf[ks][3], b0, b1);
                mma_h(Sa[2*nip+1], qf[ks][0], qf[ks][1], qf[ks][2], qf[ks][3], b2, b3);
            }
        }

        int r0g = qr + rl, r1g = qr + rl + 8;
        float mx0 = -1e30f, mx1 = -1e30f;
        #pragma unroll
        for (int ni = 0; ni < 16; ni++){
            float x0 = Sa[ni][0] * alpha, x1 = Sa[ni][1] * alpha;
            float x2 = Sa[ni][2] * alpha, x3 = Sa[ni][3] * alpha;
            if (diag){
                int kg = k0 + ni * 8 + 2 * l3;
                if (kg     > r0g) x0 = -1e30f;
                if (kg + 1 > r0g) x1 = -1e30f;
                if (kg     > r1g) x2 = -1e30f;
                if (kg + 1 > r1g) x3 = -1e30f;
            }
            Sa[ni][0]=x0; Sa[ni][1]=x1; Sa[ni][2]=x2; Sa[ni][3]=x3;
            mx0 = fmaxf(mx0, fmaxf(x0, x1));
            mx1 = fmaxf(mx1, fmaxf(x2, x3));
        }
        mx0 = fmaxf(mx0, __shfl_xor_sync(0xffffffffu, mx0, 1));
        mx0 = fmaxf(mx0, __shfl_xor_sync(0xffffffffu, mx0, 2));
        mx1 = fmaxf(mx1, __shfl_xor_sync(0xffffffffu, mx1, 1));
        mx1 = fmaxf(mx1, __shfl_xor_sync(0xffffffffu, mx1, 2));

        float mn0 = fmaxf(m0r, mx0), mn1 = fmaxf(m1r, mx1);
        float cr0 = __expf(m0r - mn0), cr1 = __expf(m1r - mn1);
        m0r = mn0; m1r = mn1;
        l0r *= cr0; l1r *= cr1;
        #pragma unroll
        for (int ni = 0; ni < 16; ni++){
            Oa[ni][0] *= cr0; Oa[ni][1] *= cr0;
            Oa[ni][2] *= cr1; Oa[ni][3] *= cr1;
        }
        float rs0 = 0.f, rs1 = 0.f;
        #pragma unroll
        for (int ni = 0; ni < 16; ni++){
            float e0 = __expf(Sa[ni][0] - mn0);
            float e1 = __expf(Sa[ni][1] - mn0);
            float e2 = __expf(Sa[ni][2] - mn1);
            float e3 = __expf(Sa[ni][3] - mn1);
            rs0 += e0 + e1; rs1 += e2 + e3;
            int colp = ni * 8 + 2 * l3;
            *(__half2*)(sPw + rl * FKSTR + colp)       = __floats2half2_rn(e0, e1);
            *(__half2*)(sPw + (rl + 8) * FKSTR + colp) = __floats2half2_rn(e2, e3);
        }
        rs0 += __shfl_xor_sync(0xffffffffu, rs0, 1);
        rs0 += __shfl_xor_sync(0xffffffffu, rs0, 2);
        rs1 += __shfl_xor_sync(0xffffffffu, rs1, 1);
        rs1 += __shfl_xor_sync(0xffffffffu, rs1, 2);
        l0r += rs0; l1r += rs1;
        __syncwarp();

        unsigned pbase = smem_u32(sPw) + parow * 2;
        #pragma unroll
        for (int ks = 0; ks < 8; ks++){
            unsigned koff = ks * 32;
            unsigned a0, a1, a2, a3;
            ldm_x4(a0, a1, a2, a3, pbase + koff);
            #pragma unroll
            for (int nip = 0; nip < 8; nip++){
                unsigned b0, b1, b2, b3;
                ldm_x4(b0, b1, b2, b3, vbase + nip * (16 * FKSTR * 2) + koff);
                mma_h(Oa[2*nip],   a0, a1, a2, a3, b0, b1);
                mma_h(Oa[2*nip+1], a0, a1, a2, a3, b2, b3);
            }
        }
        __syncthreads();
    }

    float inv0 = 1.0f / l0r, inv1 = 1.0f / l1r;
    #pragma unroll
    for (int ni = 0; ni < 16; ni++){
        int col = ni * 8 + 2 * l3;
        *(__half2*)(Og + (long long)(qr + rl) * HIDDEN + col) =
            __floats2half2_rn(Oa[ni][0] * inv0, Oa[ni][1] * inv0);
        *(__half2*)(Og + (long long)(qr + rl + 8) * HIDDEN + col) =
            __floats2half2_rn(Oa[ni][2] * inv1, Oa[ni][3] * inv1);
    }
}

// ---------------- transpose + fp16 ----------------
__global__ void transpose_h(const float* s0, __half* d0, const float* s1, __half* d1,
                            const float* s2, __half* d2, const float* s3, __half* d3,
                            int R, int C, int doInvf)
{
    __shared__ float t[32][33];
    const float* in; __half* out;
    switch (blockIdx.z){
        case 0:  in = s0; out = d0; break;
        case 1:  in = s1; out = d1; break;
        case 2:  in = s2; out = d2; break;
        default: in = s3; out = d3; break;
    }
    if (doInvf && blockIdx.x == 0 && blockIdx.y == 0 && blockIdx.z == 0){
        int f = threadIdx.y * 32 + threadIdx.x;
        if (f < 64) g_invf[f] = (float)exp(-(double)f * (log(500000.0) / 64.0));
    }
    int x  = blockIdx.x * 32 + threadIdx.x;
    int y0 = blockIdx.y * 32 + threadIdx.y;
    #pragma unroll
    for (int dy = 0; dy < 32; dy += 8)
        t[threadIdx.y + dy][threadIdx.x] = in[(long long)(y0 + dy) * C + x];
    __syncthreads();
    int ox  = blockIdx.y * 32 + threadIdx.x;
    int oy0 = blockIdx.x * 32 + threadIdx.y;
    #pragma unroll
    for (int dy = 0; dy < 32; dy += 8)
        out[(long long)(oy0 + dy) * R + ox] = __float2half_rn(t[threadIdx.x][threadIdx.y + dy]);
}

__global__ void rmsnorm_h(const float* __restrict__ X, const float* __restrict__ sc,
                          __half* __restrict__ O){
    long long base = (long long)blockIdx.x * HIDDEN;
    int tid = threadIdx.x;
    float v[8]; float ss = 0.f;
    #pragma unroll
    for (int i = 0; i < 8; i++){
        v[i] = X[base + tid + i * 256];
        ss += v[i] * v[i];
    }
    ss = blockReduceSum(ss);
    float r = rsqrtf(ss * (1.0f / (float)HIDDEN) + 1e-5f);
    #pragma unroll
    for (int i = 0; i < 8; i++){
        int c = tid + i * 256;
        O[base + c] = __float2half_rn(v[i] * r * sc[c]);
    }
}

// ---------------- launch ----------------
extern "C" void kernel_launch(void* const* d_in, const int* in_sizes, int n_in,
                              void* d_out, int out_size)
{
    const float* x   = (const float*)d_in[0];
    const int*   pos = (const int*)d_in[1];
    // d_in[2] = mask (causal; handled analytically)
    const float* wq  = (const float*)d_in[3];
    const float* wk  = (const float*)d_in[4];
    const float* wv  = (const float*)d_in[5];
    const float* wo  = (const float*)d_in[6];
    const float* asc = (const float*)d_in[7];
    const float* fsc = (const float*)d_in[8];
    const float* w1  = (const float*)d_in[9];
    const float* w3  = (const float*)d_in[10];
    const float* w2  = (const float*)d_in[11];
    float* out = (float*)d_out;

    __half *p_xnh,*p_qh,*p_kh,*p_vth,*p_aoh,*p_ffnh,*p_g1h;
    float *p_h;
    __half *p_wqkv,*p_wo,*p_w1,*p_w3,*p_w2;
    cudaGetSymbolAddress((void**)&p_xnh,  g_xnh);
    cudaGetSymbolAddress((void**)&p_qh,   g_qh);
    cudaGetSymbolAddress((void**)&p_kh,   g_kh);
    cudaGetSymbolAddress((void**)&p_vth,  g_vth);
    cudaGetSymbolAddress((void**)&p_aoh,  g_aoh);
    cudaGetSymbolAddress((void**)&p_h,    g_h);
    cudaGetSymbolAddress((void**)&p_ffnh, g_ffnh);
    cudaGetSymbolAddress((void**)&p_g1h,  g_g1h);
    cudaGetSymbolAddress((void**)&p_wqkv, g_wqkv);
    cudaGetSymbolAddress((void**)&p_wo,   g_wo);
    cudaGetSymbolAddress((void**)&p_w1,   g_w1);
    cudaGetSymbolAddress((void**)&p_w3,   g_w3);
    cudaGetSymbolAddress((void**)&p_w2,   g_w2);

    cudaFuncSetAttribute(gemm_h,   cudaFuncAttributeMaxDynamicSharedMemorySize, SMEM_H);
    cudaFuncSetAttribute(gemm_qkv, cudaFuncAttributeMaxDynamicSharedMemorySize, SMEM_H);
    cudaFuncSetAttribute(gemm_ff,  cudaFuncAttributeMaxDynamicSharedMemorySize, SMEM_F);
    cudaFuncSetAttribute(flash_h,  cudaFuncAttributeMaxDynamicSharedMemorySize, FLASH_SMEM);

    // 0. transpose + fp16 weights; wq|wk|wv concatenated into wqkv
    transpose_h<<<dim3(64,64,4), dim3(32,8)>>>(
        wq, p_wqkv,
        wk, p_wqkv + (size_t)HIDDEN*HIDDEN,
        wv, p_wqkv + (size_t)2*HIDDEN*HIDDEN,
        wo, p_wo, HIDDEN, HIDDEN, 1);
    transpose_h<<<dim3(176,64,2), dim3(32,8)>>>(w1,p_w1, w3,p_w3, nullptr,nullptr,
                                                nullptr,nullptr, HIDDEN, FFDIM, 0);
    transpose_h<<<dim3(64,176,1), dim3(32,8)>>>(w2,p_w2, nullptr,nullptr, nullptr,nullptr,
                                                nullptr,nullptr, FFDIM, HIDDEN, 0);

    // 1. rmsnorm (attn) -> fp16
    rmsnorm_h<<<NTOK,256>>>(x, asc, p_xnh);

    // 2. merged QKV projection (N=6144 -> 24 tiles of 256)
    dim3 gQKV(32*24, 1, 1);
    gemm_qkv<<<gQKV,512,SMEM_H>>>(p_xnh,HIDDEN, p_wqkv,HIDDEN,
                                  p_qh, p_kh, p_vth, pos, HIDDEN, 32,24);

    // 3. flash attention (fp16)
    flash_h<<<dim3(16, BATCHN*NHEADS),256,FLASH_SMEM>>>(
        p_qh, p_kh, p_vth, p_aoh, 0.08838834764831845f);

    // 4. h = x + attn_out @ wo   (N=2048 -> 8 tiles of 256)
    dim3 gProj(32*8, 1, 1);
    gemm_h<<<gProj,512,SMEM_H>>>(p_aoh,HIDDEN, p_wo,HIDDEN, p_h,HIDDEN,
                                 x, HIDDEN, 32,8);

    // 5. rmsnorm (ffn) -> fp16
    rmsnorm_h<<<NTOK,256>>>(p_h, fsc, p_ffnh);

    // 6. fused FFN up+gate+silu -> g1h  (N=5632 -> 44 tiles of 128)
    dim3 gFF(32*44, 1, 1);
    gemm_ff<<<gFF,512,SMEM_F>>>(p_ffnh,HIDDEN, p_w1,p_w3,HIDDEN, p_g1h,FFDIM,
                                HIDDEN, 32,44);

    // 7. out = h + g1h @ w2  (K = 5632)
    gemm_h<<<gProj,512,SMEM_H>>>(p_g1h,FFDIM, p_w2,FFDIM, out,HIDDEN,
                                 p_h, FFDIM, 32,8);
}

// round 14
// speedup vs baseline: 1.0216x; 1.0216x over previous
#include <cuda_runtime.h>
#include <cuda_fp16.h>
#include <cstdint>
#include <math.h>

#define HIDDEN 2048
#define NHEADS 16
#define HDIM 128
#define FFDIM 5632
#define BATCHN 2
#define SEQ 2048
#define NTOK (BATCHN*SEQ)   // 4096

// ---------------- scratch ----------------
__device__ __half g_xnh[NTOK*HIDDEN];
__device__ __half g_qh[NTOK*HIDDEN];
__device__ __half g_kh[NTOK*HIDDEN];
__device__ __half g_vth[BATCHN*NHEADS*HDIM*SEQ];   // V transposed: [b,h,dim,seq]
__device__ __half g_aoh[NTOK*HIDDEN];
__device__ float  g_h[NTOK*HIDDEN];
__device__ __half g_ffnh[NTOK*HIDDEN];
__device__ __half g_g1h[(size_t)NTOK*FFDIM];
__device__ float  g_invf[64];
// fp16 TRANSPOSED weights [N, K] K-major
__device__ __half g_wqkv[3*HIDDEN*HIDDEN];         // wq | wk | wv concatenated
__device__ __half g_wo[HIDDEN*HIDDEN];
__device__ __half g_w1[(size_t)HIDDEN*FFDIM];
__device__ __half g_w3[(size_t)HIDDEN*FFDIM];
__device__ __half g_w2[(size_t)FFDIM*HIDDEN];

// ---------------- helpers ----------------
__device__ __forceinline__ unsigned smem_u32(const void* p){
    return (unsigned)__cvta_generic_to_shared(p);
}
__device__ __forceinline__ void cp16(unsigned s, const void* g){
    asm volatile("cp.async.cg.shared.global [%0], [%1], 16;\n" :: "r"(s), "l"(g));
}
#define CP_COMMIT() asm volatile("cp.async.commit_group;\n")
#define CP_WAIT(n)  asm volatile("cp.async.wait_group %0;\n" :: "n"(n))

__device__ __forceinline__ void mma_h(float c[4],
        unsigned a0, unsigned a1, unsigned a2, unsigned a3,
        unsigned b0, unsigned b1){
    asm volatile("mma.sync.aligned.m16n8k16.row.col.f32.f16.f16.f32 "
        "{%0,%1,%2,%3},{%4,%5,%6,%7},{%8,%9},{%0,%1,%2,%3};\n"
        : "+f"(c[0]), "+f"(c[1]), "+f"(c[2]), "+f"(c[3])
        : "r"(a0), "r"(a1), "r"(a2), "r"(a3), "r"(b0), "r"(b1));
}
__device__ __forceinline__ void ldm_x4(unsigned &r0, unsigned &r1, unsigned &r2, unsigned &r3,
                                       unsigned addr){
    asm volatile("ldmatrix.sync.aligned.m8n8.x4.shared.b16 {%0,%1,%2,%3}, [%4];"
        : "=r"(r0), "=r"(r1), "=r"(r2), "=r"(r3) : "r"(addr));
}

__device__ __forceinline__ float warpReduceSum(float v){
    #pragma unroll
    for (int o=16;o;o>>=1) v += __shfl_xor_sync(0xffffffffu, v, o);
    return v;
}
__device__ float blockReduceSum(float v){   // 256 threads
    __shared__ float s[8]; __shared__ float tot;
    int lane = threadIdx.x & 31, w = threadIdx.x >> 5;
    v = warpReduceSum(v);
    if (!lane) s[w] = v;
    __syncthreads();
    if (w == 0){
        float t = (lane < 8) ? s[lane] : 0.f;
        t = warpReduceSum(t);
        if (!lane) tot = t;
    }
    __syncthreads();
    return tot;
}

// ======== fp16 GEMM (R12 champion): BM=BN=128, BK=64, 256 thr, 2 CTA/SM ========
#define HSTR 72
#define HTILE (128*HSTR)
#define SMEM_H (3*2*HTILE*2)             // 110592 B

__global__ void __launch_bounds__(256, 2)
gemm_h(const __half* __restrict__ A, int lda,
       const __half* __restrict__ Bt, int ldb,
       float* __restrict__ C, int ldc,
       const float* __restrict__ Res,
       int K, int npm, int npn)
{
    extern __shared__ __half sh[];

    int pid = blockIdx.x;
    const int GROUP = 16;
    int npg = GROUP * npn;
    int gid = pid / npg;
    int firstm = gid * GROUP;
    int gsz = min(GROUP, npm - firstm);
    int pm = firstm + (pid % npg) % gsz;
    int pn = (pid % npg) / gsz;
    int m0 = pm * 128, n0 = pn * 128;

    int KT = K / 64;
    int tid = threadIdx.x;
    int wid = tid >> 5, lane = tid & 31;
    int wm = (wid & 3) * 32;
    int wn = (wid >> 2) * 64;
    int rl = lane >> 2, l3 = lane & 3;

    int arow = (wm + (lane & 15)) * HSTR + (lane >> 4) * 8;
    int brow = (wn + (lane & 7) + ((lane >> 4) << 3)) * HSTR + (((lane >> 3) & 1) << 3);

    auto loadAB = [&](int st, int kt){
        __half* sa = sh + st * (2*HTILE);
        __half* sb = sa + HTILE;
        int c = tid & 7;
        int r0 = tid >> 3;
        const __half* ga = A  + (long long)m0 * lda + kt * 64 + c * 8;
        const __half* gb = Bt + (long long)n0 * ldb + kt * 64 + c * 8;
        #pragma unroll
        for (int w = 0; w < 4; w++){
            int row = r0 + 32 * w;
            cp16(smem_u32(sa + row * HSTR + c * 8), ga + (long long)row * lda);
        }
        #pragma unroll
        for (int w = 0; w < 4; w++){
            int row = r0 + 32 * w;
            cp16(smem_u32(sb + row * HSTR + c * 8), gb + (long long)row * ldb);
        }
    };

    float acc[2][8][4];
    #pragma unroll
    for (int i=0;i<2;i++)
        #pragma unroll
        for (int j=0;j<8;j++)
            #pragma unroll
            for (int r=0;r<4;r++) acc[i][j][r] = 0.f;

    loadAB(0, 0); CP_COMMIT();
    if (KT > 1) loadAB(1, 1);
    CP_COMMIT();

    for (int kt = 0; kt < KT; kt++){
        int cur = kt % 3;
        CP_WAIT(1);
        __syncthreads();
        if (kt + 2 < KT) loadAB((kt + 2) % 3, kt + 2);
        CP_COMMIT();

        const __half* sa = sh + cur * (2*HTILE);
        const __half* sb = sa + HTILE;
        unsigned abase = smem_u32(sa) + arow * 2;
        unsigned bbase = smem_u32(sb) + brow * 2;
        #pragma unroll
        for (int ks = 0; ks < 4; ks++){
            unsigned koff = ks * 32;
            unsigned a[2][4];
            #pragma unroll
            for (int mi = 0; mi < 2; mi++)
                ldm_x4(a[mi][0], a[mi][1], a[mi][2], a[mi][3],
                       abase + mi * (16 * HSTR * 2) + koff);
            #pragma unroll
            for (int nip = 0; nip < 4; nip++){
                unsigned b0, b1, b2, b3;
                ldm_x4(b0, b1, b2, b3, bbase + nip * (16 * HSTR * 2) + koff);
                #pragma unroll
                for (int mi = 0; mi < 2; mi++){
                    mma_h(acc[mi][2*nip],   a[mi][0], a[mi][1], a[mi][2], a[mi][3], b0, b1);
                    mma_h(acc[mi][2*nip+1], a[mi][0], a[mi][1], a[mi][2], a[mi][3], b2, b3);
                }
            }
        }
    }

    #pragma unroll
    for (int mi = 0; mi < 2; mi++){
        #pragma unroll
        for (int ni = 0; ni < 8; ni++){
            int row = m0 + wm + mi * 16 + rl;
            int col = n0 + wn + ni * 8 + l3 * 2;
            float v0 = acc[mi][ni][0];
            float v1 = acc[mi][ni][1];
            float v2 = acc[mi][ni][2];
            float v3 = acc[mi][ni][3];
            if (Res){
                float2 r01 = *(const float2*)(Res + (long long)row * ldc + col);
                float2 r23 = *(const float2*)(Res + (long long)(row + 8) * ldc + col);
                v0 += r01.x; v1 += r01.y; v2 += r23.x; v3 += r23.y;
            }
            *(float2*)(C + (long long)row * ldc + col)       = make_float2(v0, v1);
            *(float2*)(C + (long long)(row + 8) * ldc + col) = make_float2(v2, v3);
        }
    }
}

// ======== merged QKV gemm (R12): N=6144; epilogue rope->fp16 / V-transpose ========
__global__ void __launch_bounds__(256, 2)
gemm_qkv(const __half* __restrict__ A, int lda,
         const __half* __restrict__ Bt, int ldb,
         __half* __restrict__ Qh, __half* __restrict__ Kh, __half* __restrict__ Vt,
         const int* __restrict__ pos, int K, int npm, int npn)
{
    extern __shared__ __half sh[];

    int pid = blockIdx.x;
    const int GROUP = 16;
    int npg = GROUP * npn;
    int gid = pid / npg;
    int firstm = gid * GROUP;
    int gsz = min(GROUP, npm - firstm);
    int pm = firstm + (pid % npg) % gsz;
    int pn = (pid % npg) / gsz;
    int m0 = pm * 128, n0 = pn * 128;

    int KT = K / 64;
    int tid = threadIdx.x;
    int wid = tid >> 5, lane = tid & 31;
    int wm = (wid & 3) * 32;
    int wn = (wid >> 2) * 64;
    int rl = lane >> 2, l3 = lane & 3;

    int arow = (wm + (lane & 15)) * HSTR + (lane >> 4) * 8;
    int brow = (wn + (lane & 7) + ((lane >> 4) << 3)) * HSTR + (((lane >> 3) & 1) << 3);

    auto loadAB = [&](int st, int kt){
        __half* sa = sh + st * (2*HTILE);
        __half* sb = sa + HTILE;
        int c = tid & 7;
        int r0 = tid >> 3;
        const __half* ga = A  + (long long)m0 * lda + kt * 64 + c * 8;
        const __half* gb = Bt + (long long)n0 * ldb + kt * 64 + c * 8;
        #pragma unroll
        for (int w = 0; w < 4; w++){
            int row = r0 + 32 * w;
            cp16(smem_u32(sa + row * HSTR + c * 8), ga + (long long)row * lda);
        }
        #pragma unroll
        for (int w = 0; w < 4; w++){
            int row = r0 + 32 * w;
            cp16(smem_u32(sb + row * HSTR + c * 8), gb + (long long)row * ldb);
        }
    };

    float acc[2][8][4];
    #pragma unroll
    for (int i=0;i<2;i++)
        #pragma unroll
        for (int j=0;j<8;j++)
            #pragma unroll
            for (int r=0;r<4;r++) acc[i][j][r] = 0.f;

    loadAB(0, 0); CP_COMMIT();
    if (KT > 1) loadAB(1, 1);
    CP_COMMIT();

    for (int kt = 0; kt < KT; kt++){
        int cur = kt % 3;
        CP_WAIT(1);
        __syncthreads();
        if (kt + 2 < KT) loadAB((kt + 2) % 3, kt + 2);
        CP_COMMIT();

        const __half* sa = sh + cur * (2*HTILE);
        const __half* sb = sa + HTILE;
        unsigned abase = smem_u32(sa) + arow * 2;
        unsigned bbase = smem_u32(sb) + brow * 2;
        #pragma unroll
        for (int ks = 0; ks < 4; ks++){
            unsigned koff = ks * 32;
            unsigned a[2][4];
            #pragma unroll
            for (int mi = 0; mi < 2; mi++)
                ldm_x4(a[mi][0], a[mi][1], a[mi][2], a[mi][3],
                       abase + mi * (16 * HSTR * 2) + koff);
            #pragma unroll
            for (int nip = 0; nip < 4; nip++){
                unsigned b0, b1, b2, b3;
                ldm_x4(b0, b1, b2, b3, bbase + nip * (16 * HSTR * 2) + koff);
                #pragma unroll
                for (int mi = 0; mi < 2; mi++){
                    mma_h(acc[mi][2*nip],   a[mi][0], a[mi][1], a[mi][2], a[mi][3], b0, b1);
                    mma_h(acc[mi][2*nip+1], a[mi][0], a[mi][1], a[mi][2], a[mi][3], b2, b3);
                }
            }
        }
    }

    int wsel = n0 >> 11;          // 0=q, 1=k, 2=v
    int n0l  = n0 & 2047;
    #pragma unroll
    for (int mi = 0; mi < 2; mi++){
        #pragma unroll
        for (int ni = 0; ni < 8; ni++){
            int row = m0 + wm + mi * 16 + rl;
            int col = n0l + wn + ni * 8 + l3 * 2;
            float v0 = acc[mi][ni][0];
            float v1 = acc[mi][ni][1];
            float v2 = acc[mi][ni][2];
            float v3 = acc[mi][ni][3];
            if (wsel < 2){
                int i = (col & 127) >> 1;
                float invf = g_invf[i];
                float a0 = (float)pos[row] * invf;
                float a1 = (float)pos[row + 8] * invf;
                float s0, c0, s1, c1;
                sincosf(a0, &s0, &c0);
                sincosf(a1, &s1, &c1);
                float t0 = v0 * c0 - v1 * s0;
                float t1 = v1 * c0 + v0 * s0;
                float t2 = v2 * c1 - v3 * s1;
                float t3 = v3 * c1 + v2 * s1;
                __half* O = wsel ? Kh : Qh;
                *(__half2*)(O + (long long)row * 2048 + col)       = __floats2half2_rn(t0, t1);
                *(__half2*)(O + (long long)(row + 8) * 2048 + col) = __floats2half2_rn(t2, t3);
            } else {
                int b = row >> 11, seq = row & 2047;
                int h = col >> 7,  dim = col & 127;
                __half* base = Vt + ((long long)(b * 16 + h) * 128) * 2048;
                base[(long long)dim * 2048 + seq]           = __float2half_rn(v0);
                base[(long long)(dim + 1) * 2048 + seq]     = __float2half_rn(v1);
                base[(long long)dim * 2048 + seq + 8]       = __float2half_rn(v2);
                base[(long long)(dim + 1) * 2048 + seq + 8] = __float2half_rn(v3);
            }
        }
    }
}

// ======== fused FFN (R12): g1h = fp16( silu(A@W1^T) * (A@W3^T) ) ========
#define FBTILE (64*HSTR)
#define FSTAGE (HTILE + 2*FBTILE)
#define SMEM_F (3*FSTAGE*2)              // 110592 B

__global__ void __launch_bounds__(256, 2)
gemm_ff(const __half* __restrict__ A, int lda,
        const __half* __restrict__ B1t, const __half* __restrict__ B3t, int ldb,
        __half* __restrict__ O, int ldo,
        int K, int npm, int npn)
{
    extern __shared__ __half sh[];

    int pid = blockIdx.x;
    const int GROUP = 16;
    int npg = GROUP * npn;
    int gid = pid / npg;
    int firstm = gid * GROUP;
    int gsz = min(GROUP, npm - firstm);
    int pm = firstm + (pid % npg) % gsz;
    int pn = (pid % npg) / gsz;
    int m0 = pm * 128, n0 = pn * 64;

    int KT = K / 64;
    int tid = threadIdx.x;
    int wid = tid >> 5, lane = tid & 31;
    int wm = (wid & 3) * 32;
    int wn = (wid >> 2) * 32;
    int rl = lane >> 2, l3 = lane & 3;

    int arow = (wm + (lane & 15)) * HSTR + (lane >> 4) * 8;
    int brow = (wn + (lane & 7) + ((lane >> 4) << 3)) * HSTR + (((lane >> 3) & 1) << 3);

    auto loadAB = [&](int st, int kt){
        __half* sa = sh + st * FSTAGE;
        __half* sb1 = sa + HTILE;
        __half* sb3 = sb1 + FBTILE;
        int c = tid & 7;
        int r0 = tid >> 3;
        const __half* ga = A + (long long)m0 * lda + kt * 64 + c * 8;
        #pragma unroll
        for (int w = 0; w < 4; w++){
            int row = r0 + 32 * w;
            cp16(smem_u32(sa + row * HSTR + c * 8), ga + (long long)row * lda);
        }
        const __half* g1 = B1t + (long long)n0 * ldb + kt * 64 + c * 8;
        const __half* g3 = B3t + (long long)n0 * ldb + kt * 64 + c * 8;
        #pragma unroll
        for (int w = 0; w < 2; w++){
            int row = r0 + 32 * w;
            cp16(smem_u32(sb1 + row * HSTR + c * 8), g1 + (long long)row * ldb);
        }
        #pragma unroll
        for (int w = 0; w < 2; w++){
            int row = r0 + 32 * w;
            cp16(smem_u32(sb3 + row * HSTR + c * 8), g3 + (long long)row * ldb);
        }
    };

    float ac1[2][4][4], ac3[2][4][4];
    #pragma unroll
    for (int i=0;i<2;i++)
        #pragma unroll
        for (int j=0;j<4;j++)
            #pragma unroll
            for (int r=0;r<4;r++){ ac1[i][j][r] = 0.f; ac3[i][j][r] = 0.f; }

    loadAB(0, 0); CP_COMMIT();
    if (KT > 1) loadAB(1, 1);
    CP_COMMIT();

    for (int kt = 0; kt < KT; kt++){
        int cur = kt % 3;
        CP_WAIT(1);
        __syncthreads();
        if (kt + 2 < KT) loadAB((kt + 2) % 3, kt + 2);
        CP_COMMIT();

        const __half* sa  = sh + cur * FSTAGE;
        const __half* sb1 = sa + HTILE;
        const __half* sb3 = sb1 + FBTILE;
        unsigned abase  = smem_u32(sa)  + arow * 2;
        unsigned b1base = smem_u32(sb1) + brow * 2;
        unsigned b3base = smem_u32(sb3) + brow * 2;
        #pragma unroll
        for (int ks = 0; ks < 4; ks++){
            unsigned koff = ks * 32;
            unsigned a[2][4];
            #pragma unroll
            for (int mi = 0; mi < 2; mi++)
                ldm_x4(a[mi][0], a[mi][1], a[mi][2], a[mi][3],
                       abase + mi * (16 * HSTR * 2) + koff);
            #pragma unroll
            for (int nip = 0; nip < 2; nip++){
                unsigned b0, b1, b2, b3;
                ldm_x4(b0, b1, b2, b3, b1base + nip * (16 * HSTR * 2) + koff);
                #pragma unroll
                for (int mi = 0; mi < 2; mi++){
                    mma_h(ac1[mi][2*nip],   a[mi][0], a[mi][1], a[mi][2], a[mi][3], b0, b1);
                    mma_h(ac1[mi][2*nip+1], a[mi][0], a[mi][1], a[mi][2], a[mi][3], b2, b3);
                }
                unsigned c0, c1, c2, c3;
                ldm_x4(c0, c1, c2, c3, b3base + nip * (16 * HSTR * 2) + koff);
                #pragma unroll
                for (int mi = 0; mi < 2; mi++){
                    mma_h(ac3[mi][2*nip],   a[mi][0], a[mi][1], a[mi][2], a[mi][3], c0, c1);
                    mma_h(ac3[mi][2*nip+1], a[mi][0], a[mi][1], a[mi][2], a[mi][3], c2, c3);
                }
            }
        }
    }

    #pragma unroll
    for (int mi = 0; mi < 2; mi++){
        #pragma unroll
        for (int ni = 0; ni < 4; ni++){
            int row = m0 + wm + mi * 16 + rl;
            int col = n0 + wn + ni * 8 + l3 * 2;
            float x0 = ac1[mi][ni][0], x1 = ac1[mi][ni][1];
            float x2 = ac1[mi][ni][2], x3 = ac1[mi][ni][3];
            float y0 = ac3[mi][ni][0], y1 = ac3[mi][ni][1];
            float y2 = ac3[mi][ni][2], y3 = ac3[mi][ni][3];
            float s0 = x0 / (1.0f + __expf(-x0)) * y0;
            float s1 = x1 / (1.0f + __expf(-x1)) * y1;
            float s2 = x2 / (1.0f + __expf(-x2)) * y2;
            float s3 = x3 / (1.0f + __expf(-x3)) * y3;
            *(__half2*)(O + (long long)row * ldo + col)       = __floats2half2_rn(s0, s1);
            *(__half2*)(O + (long long)(row + 8) * ldo + col) = __floats2half2_rn(s2, s3);
        }
    }
}

// ---------------- flash attention v5: fp16, 64-key tiles, 2 CTAs/SM ----------------
// sK 2x[64][136], sVt 2x[128][72], sP 8x[16][72]  = 90112 B
#define KST2 136
#define VST2 72
#define PST2 72
#define FLASH_SMEM ((2*64*KST2 + 2*128*VST2 + 8*16*PST2)*2)   // 90112

__global__ void __launch_bounds__(256, 2)
flash_h(const __half* __restrict__ Q, const __half* __restrict__ K,
        const __half* __restrict__ Vt, __half* __restrict__ O,
        float alpha)
{
    extern __shared__ __half sh[];
    __half* sKb  = sh;                       // 2 x 64*136
    __half* sVtb = sh + 2*64*KST2;           // 2 x 128*72
    __half* sP   = sVtb + 2*128*VST2;        // 8 x 16*72

    int z = blockIdx.y;
    int b = z >> 4, h = z & 15;
    int qt = (gridDim.x - 1) - blockIdx.x;   // heavy tiles first
    int q0 = qt * 128;
    const __half* Qg  = Q + ((long long)b * SEQ) * HIDDEN + h * HDIM;
    const __half* Kg  = K + ((long long)b * SEQ) * HIDDEN + h * HDIM;
    const __half* Vtg = Vt + ((long long)z * HDIM) * SEQ;
    __half* Og = O + ((long long)b * SEQ) * HIDDEN + h * HDIM;

    int tid = threadIdx.x, wid = tid >> 5, lane = tid & 31;
    int rl = lane >> 2, l3 = lane & 3;
    int qr = q0 + wid * 16;
    __half* sPw = sP + wid * 16 * PST2;

    int brow_k = ((lane & 7) + ((lane >> 4) << 3)) * KST2 + (((lane >> 3) & 1) << 3);
    int brow_v = ((lane & 7) + ((lane >> 4) << 3)) * VST2 + (((lane >> 3) & 1) << 3);
    int parow  = (lane & 15) * PST2 + ((lane >> 4) << 3);

    // Q fragments (fp16): 8 k16 steps x 4 regs
    unsigned qf[8][4];
    #pragma unroll
    for (int ks = 0; ks < 8; ks++){
        const __half* p0 = Qg + (long long)(qr + rl) * HIDDEN + ks * 16 + l3 * 2;
        const __half* p1 = Qg + (long long)(qr + rl + 8) * HIDDEN + ks * 16 + l3 * 2;
        qf[ks][0] = *(const unsigned*)(p0);
        qf[ks][1] = *(const unsigned*)(p1);
        qf[ks][2] = *(const unsigned*)(p0 + 8);
        qf[ks][3] = *(const unsigned*)(p1 + 8);
    }

    float Oa[16][4];
    #pragma unroll
    for (int ni = 0; ni < 16; ni++){
        Oa[ni][0] = 0.f; Oa[ni][1] = 0.f; Oa[ni][2] = 0.f; Oa[ni][3] = 0.f;
    }
    float m0r = -1e30f, m1r = -1e30f, l0r = 0.f, l1r = 0.f;

    // one commit group per 64-key tile: K [64 keys x 128 dims] + Vt [128 dims x 64 keys]
    auto loadKV = [&](int buf, int t){
        int ck = tid & 15, rk = tid >> 4;        // K: 16 chunks/row, 16 rows/pass
        const __half* kp = Kg + (long long)(t * 64) * HIDDEN + ck * 8;
        __half* dk = sKb + buf * 64 * KST2;
        #pragma unroll
        for (int w = 0; w < 4; w++){
            int row = rk + 16 * w;
            cp16(smem_u32(dk + row * KST2 + ck * 8), kp + (long long)row * HIDDEN);
        }
        int cv = tid & 7, rv = tid >> 3;         // Vt: 8 chunks/row, 32 rows/pass
        const __half* vp = Vtg + t * 64 + cv * 8;
        __half* dv = sVtb + buf * 128 * VST2;
        #pragma unroll
        for (int w = 0; w < 4; w++){
            int row = rv + 32 * w;               // dim index
            cp16(smem_u32(dv + row * VST2 + cv * 8), vp + (long long)row * SEQ);
        }
    };

    int nt = 2 * qt + 2;
    loadKV(0, 0); CP_COMMIT();

    for (int t = 0; t < nt; t++){
        int buf = t & 1;
        if (t + 1 < nt){
            loadKV(buf ^ 1, t + 1);
            CP_COMMIT();
            CP_WAIT(1);
        } else {
            CP_WAIT(0);
        }
        __syncthreads();
        const __half* cK  = sKb  + buf * 64 * KST2;
        const __half* cVt = sVtb + buf * 128 * VST2;
        unsigned kbase = smem_u32(cK)  + brow_k * 2;
        unsigned vbase = smem_u32(cVt) + brow_v * 2;
        int diag = (t >= 2 * qt);
        int k0 = t * 64;

        // S = Q @ K^T over 64 keys (4 ldmatrix x4 per k-step)
        float Sa[8][4];
        #pragma unroll
        for (int ni = 0; ni < 8; ni++){
            Sa[ni][0]=0.f; Sa[ni][1]=0.f; Sa[ni][2]=0.f; Sa[ni][3]=0.f;
        }
        #pragma unroll
        for (int ks = 0; ks < 8; ks++){
            unsigned koff = ks * 32;
            #pragma unroll
            for (int nip = 0; nip < 4; nip++){
                unsigned b0, b1, b2, b3;
                ldm_x4(b0, b1, b2, b3, kbase + nip * (16 * KST2 * 2) + koff);
                mma_h(Sa[2*nip],   qf[ks][0], qf[ks][1], qf[ks][2], qf[ks][3], b0, b1);
                mma_h(Sa[2*nip+1], qf[ks][0], qf[ks][1], qf[ks][2], qf[ks][3], b2, b3);
            }
        }

        // scale + causal mask + row max
        int r0g = qr + rl, r1g = qr + rl + 8;
        float mx0 = -1e30f, mx1 = -1e30f;
        #pragma unroll
        for (int ni = 0; ni < 8; ni++){
            float x0 = Sa[ni][0] * alpha, x1 = Sa[ni][1] * alpha;
            float x2 = Sa[ni][2] * alpha, x3 = Sa[ni][3] * alpha;
            if (diag){
                int kg = k0 + ni * 8 + 2 * l3;
                if (kg     > r0g) x0 = -1e30f;
                if (kg + 1 > r0g) x1 = -1e30f;
                if (kg     > r1g) x2 = -1e30f;
                if (kg + 1 > r1g) x3 = -1e30f;
            }
            Sa[ni][0]=x0; Sa[ni][1]=x1; Sa[ni][2]=x2; Sa[ni][3]=x3;
            mx0 = fmaxf(mx0, fmaxf(x0, x1));
            mx1 = fmaxf(mx1, fmaxf(x2, x3));
        }
        mx0 = fmaxf(mx0, __shfl_xor_sync(0xffffffffu, mx0, 1));
        mx0 = fmaxf(mx0, __shfl_xor_sync(0xffffffffu, mx0, 2));
        mx1 = fmaxf(mx1, __shfl_xor_sync(0xffffffffu, mx1, 1));
        mx1 = fmaxf(mx1, __shfl_xor_sync(0xffffffffu, mx1, 2));

        float mn0 = fmaxf(m0r, mx0), mn1 = fmaxf(m1r, mx1);
        float cr0 = __expf(m0r - mn0), cr1 = __expf(m1r - mn1);
        m0r = mn0; m1r = mn1;
        l0r *= cr0; l1r *= cr1;
        #pragma unroll
        for (int ni = 0; ni < 16; ni++){
            Oa[ni][0] *= cr0; Oa[ni][1] *= cr0;
            Oa[ni][2] *= cr1; Oa[ni][3] *= cr1;
        }
        float rs0 = 0.f, rs1 = 0.f;
        #pragma unroll
        for (int ni = 0; ni < 8; ni++){
            float e0 = __expf(Sa[ni][0] - mn0);
            float e1 = __expf(Sa[ni][1] - mn0);
            float e2 = __expf(Sa[ni][2] - mn1);
            float e3 = __expf(Sa[ni][3] - mn1);
            rs0 += e0 + e1; rs1 += e2 + e3;
            int colp = ni * 8 + 2 * l3;
            *(__half2*)(sPw + rl * PST2 + colp)       = __floats2half2_rn(e0, e1);
            *(__half2*)(sPw + (rl + 8) * PST2 + colp) = __floats2half2_rn(e2, e3);
        }
        rs0 += __shfl_xor_sync(0xffffffffu, rs0, 1);
        rs0 += __shfl_xor_sync(0xffffffffu, rs0, 2);
        rs1 += __shfl_xor_sync(0xffffffffu, rs1, 1);
        rs1 += __shfl_xor_sync(0xffffffffu, rs1, 2);
        l0r += rs0; l1r += rs1;
        __syncwarp();

        // O += P @ V : k = 64 keys (4 k16 steps), n = 128 dims (8 x4 loads)
        unsigned pbase = smem_u32(sPw) + parow * 2;
        #pragma unroll
        for (int ks = 0; ks < 4; ks++){
            unsigned koff = ks * 32;
            unsigned a0, a1, a2, a3;
            ldm_x4(a0, a1, a2, a3, pbase + koff);
            #pragma unroll
            for (int nip = 0; nip < 8; nip++){
                unsigned b0, b1, b2, b3;
                ldm_x4(b0, b1, b2, b3, vbase + nip * (16 * VST2 * 2) + koff);
                mma_h(Oa[2*nip],   a0, a1, a2, a3, b0, b1);
                mma_h(Oa[2*nip+1], a0, a1, a2, a3, b2, b3);
            }
        }
        __syncthreads();
    }

    // normalize + write fp16
    float inv0 = 1.0f / l0r, inv1 = 1.0f / l1r;
    #pragma unroll
    for (int ni = 0; ni < 16; ni++){
        int col = ni * 8 + 2 * l3;
        *(__half2*)(Og + (long long)(qr + rl) * HIDDEN + col) =
            __floats2half2_rn(Oa[ni][0] * inv0, Oa[ni][1] * inv0);
        *(__half2*)(Og + (long long)(qr + rl + 8) * HIDDEN + col) =
            __floats2half2_rn(Oa[ni][2] * inv1, Oa[ni][3] * inv1);
    }
}

// ---------------- transpose + fp16 ----------------
__global__ void transpose_h(const float* s0, __half* d0, const float* s1, __half* d1,
                            const float* s2, __half* d2, const float* s3, __half* d3,
                            int R, int C, int doInvf)
{
    __shared__ float t[32][33];
    const float* in; __half* out;
    switch (blockIdx.z){
        case 0:  in = s0; out = d0; break;
        case 1:  in = s1; out = d1; break;
        case 2:  in = s2; out = d2; break;
        default: in = s3; out = d3; break;
    }
    if (doInvf && blockIdx.x == 0 && blockIdx.y == 0 && blockIdx.z == 0){
        int f = threadIdx.y * 32 + threadIdx.x;
        if (f < 64) g_invf[f] = (float)exp(-(double)f * (log(500000.0) / 64.0));
    }
    int x  = blockIdx.x * 32 + threadIdx.x;
    int y0 = blockIdx.y * 32 + threadIdx.y;
    #pragma unroll
    for (int dy = 0; dy < 32; dy += 8)
        t[threadIdx.y + dy][threadIdx.x] = in[(long long)(y0 + dy) * C + x];
    __syncthreads();
    int ox  = blockIdx.y * 32 + threadIdx.x;
    int oy0 = blockIdx.x * 32 + threadIdx.y;
    #pragma unroll
    for (int dy = 0; dy < 32; dy += 8)
        out[(long long)(oy0 + dy) * R + ox] = __float2half_rn(t[threadIdx.x][threadIdx.y + dy]);
}

__global__ void rmsnorm_h(const float* __restrict__ X, const float* __restrict__ sc,
                          __half* __restrict__ O){
    long long base = (long long)blockIdx.x * HIDDEN;
    int tid = threadIdx.x;
    float v[8]; float ss = 0.f;
    #pragma unroll
    for (int i = 0; i < 8; i++){
        v[i] = X[base + tid + i * 256];
        ss += v[i] * v[i];
    }
    ss = blockReduceSum(ss);
    float r = rsqrtf(ss * (1.0f / (float)HIDDEN) + 1e-5f);
    #pragma unroll
    for (int i = 0; i < 8; i++){
        int c = tid + i * 256;
        O[base + c] = __float2half_rn(v[i] * r * sc[c]);
    }
}

// ---------------- launch ----------------
extern "C" void kernel_launch(void* const* d_in, const int* in_sizes, int n_in,
                              void* d_out, int out_size)
{
    const float* x   = (const float*)d_in[0];
    const int*   pos = (const int*)d_in[1];
    // d_in[2] = mask (causal; handled analytically)
    const float* wq  = (const float*)d_in[3];
    const float* wk  = (const float*)d_in[4];
    const float* wv  = (const float*)d_in[5];
    const float* wo  = (const float*)d_in[6];
    const float* asc = (const float*)d_in[7];
    const float* fsc = (const float*)d_in[8];
    const float* w1  = (const float*)d_in[9];
    const float* w3  = (const float*)d_in[10];
    const float* w2  = (const float*)d_in[11];
    float* out = (float*)d_out;

    __half *p_xnh,*p_qh,*p_kh,*p_vth,*p_aoh,*p_ffnh,*p_g1h;
    float *p_h;
    __half *p_wqkv,*p_wo,*p_w1,*p_w3,*p_w2;
    cudaGetSymbolAddress((void**)&p_xnh,  g_xnh);
    cudaGetSymbolAddress((void**)&p_qh,   g_qh);
    cudaGetSymbolAddress((void**)&p_kh,   g_kh);
    cudaGetSymbolAddress((void**)&p_vth,  g_vth);
    cudaGetSymbolAddress((void**)&p_aoh,  g_aoh);
    cudaGetSymbolAddress((void**)&p_h,    g_h);
    cudaGetSymbolAddress((void**)&p_ffnh, g_ffnh);
    cudaGetSymbolAddress((void**)&p_g1h,  g_g1h);
    cudaGetSymbolAddress((void**)&p_wqkv, g_wqkv);
    cudaGetSymbolAddress((void**)&p_wo,   g_wo);
    cudaGetSymbolAddress((void**)&p_w1,   g_w1);
    cudaGetSymbolAddress((void**)&p_w3,   g_w3);
    cudaGetSymbolAddress((void**)&p_w2,   g_w2);

    cudaFuncSetAttribute(gemm_h,   cudaFuncAttributeMaxDynamicSharedMemorySize, SMEM_H);
    cudaFuncSetAttribute(gemm_qkv, cudaFuncAttributeMaxDynamicSharedMemorySize, SMEM_H);
    cudaFuncSetAttribute(gemm_ff,  cudaFuncAttributeMaxDynamicSharedMemorySize, SMEM_F);
    cudaFuncSetAttribute(flash_h,  cudaFuncAttributeMaxDynamicSharedMemorySize, FLASH_SMEM);

    // 0. transpose + fp16 weights; wq|wk|wv concatenated into wqkv
    transpose_h<<<dim3(64,64,4), dim3(32,8)>>>(
        wq, p_wqkv,
        wk, p_wqkv + (size_t)HIDDEN*HIDDEN,
        wv, p_wqkv + (size_t)2*HIDDEN*HIDDEN,
        wo, p_wo, HIDDEN, HIDDEN, 1);
    transpose_h<<<dim3(176,64,2), dim3(32,8)>>>(w1,p_w1, w3,p_w3, nullptr,nullptr,
                                                nullptr,nullptr, HIDDEN, FFDIM, 0);
    transpose_h<<<dim3(64,176,1), dim3(32,8)>>>(w2,p_w2, nullptr,nullptr, nullptr,nullptr,
                                                nullptr,nullptr, FFDIM, HIDDEN, 0);

    // 1. rmsnorm (attn) -> fp16
    rmsnorm_h<<<NTOK,256>>>(x, asc, p_xnh);

    // 2. merged QKV projection (N=6144), rope->fp16 q/k, transposed fp16 v
    dim3 gQKV(32*48, 1, 1);
    gemm_qkv<<<gQKV,256,SMEM_H>>>(p_xnh,HIDDEN, p_wqkv,HIDDEN,
                                  p_qh, p_kh, p_vth, pos, HIDDEN, 32,48);

    // 3. flash attention (fp16, 64-key tiles, 2 CTAs/SM)
    flash_h<<<dim3(16, BATCHN*NHEADS),256,FLASH_SMEM>>>(
        p_qh, p_kh, p_vth, p_aoh, 0.08838834764831845f);

    // 4. h = x + attn_out @ wo
    dim3 gProj(32*16, 1, 1);
    gemm_h<<<gProj,256,SMEM_H>>>(p_aoh,HIDDEN, p_wo,HIDDEN, p_h,HIDDEN,
                                 x, HIDDEN, 32,16);

    // 5. rmsnorm (ffn) -> fp16
    rmsnorm_h<<<NTOK,256>>>(p_h, fsc, p_ffnh);

    // 6. fused FFN up+gate+silu -> g1h
    dim3 gFF(32*88, 1, 1);
    gemm_ff<<<gFF,256,SMEM_F>>>(p_ffnh,HIDDEN, p_w1,p_w3,HIDDEN, p_g1h,FFDIM,
                                HIDDEN, 32,88);

    // 7. out = h + g1h @ w2  (K = 5632)
    gemm_h<<<gProj,256,SMEM_H>>>(p_g1h,FFDIM, p_w2,FFDIM, out,HIDDEN,
                                 p_h, FFDIM, 32,16);
}